// round 2
// baseline (speedup 1.0000x reference)
#include <cuda_runtime.h>
#include <math.h>
#include <stdint.h>

#define Bsz 4
#define Nq  8192
#define Mp  2048
#define C1  128
#define C2  256
#define CIN 384
#define CO0 256
#define CO1 128
#define NC  (Bsz*Nq)   // 32768

// packed f32x2 FMA (ptxas never auto-fuses this; PTX-only)
#define FMA_F32X2(d, a, b, c) \
    asm("fma.rn.f32x2 %0, %1, %2, %3;" : "=l"(d) : "l"(a), "l"(b), "l"(c))

union F2U { uint64_t u; float2 f; };

// ---------------- scratch (static device globals; no allocation) ----------------
__device__ float g_p2T[Bsz*Mp*C2];            // points2 transposed (B,M,C2)   8 MB
__device__ float g_X[(size_t)NC*CIN];         // concat input, layout [col][k] 50 MB
__device__ float g_Y0[(size_t)CO0*NC];        // conv0 raw output [o][col]     33 MB
__device__ float g_scale0[CO0], g_shift0[CO0];
__device__ float g_scale1[CO1], g_shift1[CO1];

// ---------------- transpose: in (B,R,C) -> out[(b*C+c)*ostride + ooff + r] ------
__global__ void transpose_kernel(const float* __restrict__ in, float* __restrict__ out,
                                 int R, int C, int ostride, int ooff)
{
    __shared__ float tile[32][33];
    int b  = blockIdx.z;
    int c0 = blockIdx.x * 32;
    int r0 = blockIdx.y * 32;
    const float* ip = in + (size_t)b * R * C;
#pragma unroll
    for (int s = 0; s < 4; s++) {
        int r = r0 + threadIdx.y + 8*s;
        tile[threadIdx.y + 8*s][threadIdx.x] = ip[(size_t)r * C + c0 + threadIdx.x];
    }
    __syncthreads();
#pragma unroll
    for (int s = 0; s < 4; s++) {
        int c = c0 + threadIdx.y + 8*s;
        out[((size_t)b * C + c) * ostride + ooff + r0 + threadIdx.x] = tile[threadIdx.x][threadIdx.y + 8*s];
    }
}

// ---------------- 3-NN + weights + interpolation -> g_X[col][0..255] -----------
__global__ __launch_bounds__(128) void knn_interp_kernel(
    const float* __restrict__ xyz1, const float* __restrict__ xyz2,
    const float* __restrict__ norm1, const float* __restrict__ norm2)
{
    __shared__ float4 sp[Mp];   // {px, py, pz, pp}  32 KB
    int b = blockIdx.y;
    const float* x2 = xyz2 + (size_t)b * 3 * Mp;
    for (int m = threadIdx.x; m < Mp; m += 128) {
        float a = x2[m], c = x2[Mp + m], d = x2[2*Mp + m];
        float4 v; v.x = a; v.y = c; v.z = d; v.w = a*a + c*c + d*d;
        sp[m] = v;
    }
    __syncthreads();

    int n = blockIdx.x * 128 + threadIdx.x;
    const float* x1 = xyz1 + (size_t)b * 3 * Nq;
    float qx = x1[n], qy = x1[Nq + n], qz = x1[2*Nq + n];
    float qq = qx*qx + qy*qy + qz*qz;

    float d2_0 = 1e30f, d2_1 = 1e30f, d2_2 = 1e30f;
    int   i0 = 0, i1 = 0, i2 = 0;
#pragma unroll 4
    for (int m = 0; m < Mp; m++) {
        float4 P = sp[m];
        float dot = qx*P.x + qy*P.y + qz*P.z;
        float d2  = qq + P.w - 2.0f*dot;          // matches reference's expanded form
        if (d2 < d2_2) {                           // strict < : ties keep lower index
            if (d2 < d2_1) {
                d2_2 = d2_1; i2 = i1;
                if (d2 < d2_0) { d2_1 = d2_0; i1 = i0; d2_0 = d2; i0 = m; }
                else           { d2_1 = d2;  i1 = m; }
            } else { d2_2 = d2; i2 = m; }
        }
    }
    float dist0 = sqrtf(fmaxf(d2_0, 1e-20f));
    float dist1 = sqrtf(fmaxf(d2_1, 1e-20f));
    float dist2 = sqrtf(fmaxf(d2_2, 1e-20f));

    const float* n1 = norm1 + (size_t)b * 3 * Nq;
    const float* n2 = norm2 + (size_t)b * 3 * Mp;
    float ax = n1[n], ay = n1[Nq+n], az = n1[2*Nq+n];
    float dx, dy, dz;
    dx = ax - n2[i0]; dy = ay - n2[Mp+i0]; dz = az - n2[2*Mp+i0];
    float nd0 = sqrtf(dx*dx + dy*dy + dz*dz);
    dx = ax - n2[i1]; dy = ay - n2[Mp+i1]; dz = az - n2[2*Mp+i1];
    float nd1 = sqrtf(dx*dx + dy*dy + dz*dz);
    dx = ax - n2[i2]; dy = ay - n2[Mp+i2]; dz = az - n2[2*Mp+i2];
    float nd2 = sqrtf(dx*dx + dy*dy + dz*dz);

    float r0 = 1.0f / fmaxf(dist0, 1e-10f);
    float r1 = 1.0f / fmaxf(dist1, 1e-10f);
    float r2 = 1.0f / fmaxf(dist2, 1e-10f);
    float rs = r0 + r1 + r2;
    float s0 = 1.0f / fmaxf(nd0, 1e-10f);
    float s1 = 1.0f / fmaxf(nd1, 1e-10f);
    float s2 = 1.0f / fmaxf(nd2, 1e-10f);
    float ssum = s0 + s1 + s2;
    float w0 = (r0 / rs) * (s0 / ssum);
    float w1 = (r1 / rs) * (s1 / ssum);
    float w2 = (r2 / rs) * (s2 / ssum);

    size_t col = (size_t)b * Nq + n;
    const float4* p0 = (const float4*)(g_p2T + ((size_t)b*Mp + i0) * C2);
    const float4* p1 = (const float4*)(g_p2T + ((size_t)b*Mp + i1) * C2);
    const float4* p2 = (const float4*)(g_p2T + ((size_t)b*Mp + i2) * C2);
    float4* xo = (float4*)(g_X + col * CIN);
#pragma unroll 4
    for (int c = 0; c < C2/4; c++) {
        float4 a = p0[c], bq = p1[c], cq = p2[c];
        float4 r;
        r.x = w0*a.x + w1*bq.x + w2*cq.x;
        r.y = w0*a.y + w1*bq.y + w2*cq.y;
        r.z = w0*a.z + w1*bq.z + w2*cq.z;
        r.w = w0*a.w + w1*bq.w + w2*cq.w;
        xo[c] = r;
    }
}

// ---------------- GEMM0: Y0[o][col] = W0(256x384) @ X^T + b0 -------------------
// A stored DUPLICATED in smem ({v,v} per element) so inner loop uses LDS.64 + FFMA2.
__global__ __launch_bounds__(256, 2) void gemm0_kernel(const float* __restrict__ A,
                                                       const float* __restrict__ bias)
{
    __shared__ float As2[128*32];  // [row][2k] duplicated, stride 32  (16 KB)
    __shared__ float Bs[16*132];   // [k][col], stride 132 (16B-aligned rows)
    int t  = threadIdx.x;
    int c0 = blockIdx.x * 128;
    int m0 = blockIdx.y * 128;
    int tx = t & 15, ty = t >> 4;
    uint64_t acc[8][4];
#pragma unroll
    for (int i = 0; i < 8; i++)
#pragma unroll
        for (int j = 0; j < 4; j++) acc[i][j] = 0ull;

    for (int kk = 0; kk < CIN; kk += 16) {
        if (t < 128) {
            const float* ap = A + (size_t)(m0 + t) * CIN + kk;
            float2* as = (float2*)&As2[t*32];
#pragma unroll
            for (int q = 0; q < 4; q++) {
                float4 v = *(const float4*)(ap + 4*q);
                as[4*q+0] = make_float2(v.x, v.x);
                as[4*q+1] = make_float2(v.y, v.y);
                as[4*q+2] = make_float2(v.z, v.z);
                as[4*q+3] = make_float2(v.w, v.w);
            }
        } else {
            int colv = t - 128;
            const float* xp = g_X + (size_t)(c0 + colv) * CIN + kk;
            float4 v0 = *(const float4*)(xp);
            float4 v1 = *(const float4*)(xp+4);
            float4 v2 = *(const float4*)(xp+8);
            float4 v3 = *(const float4*)(xp+12);
            Bs[ 0*132+colv]=v0.x; Bs[ 1*132+colv]=v0.y; Bs[ 2*132+colv]=v0.z; Bs[ 3*132+colv]=v0.w;
            Bs[ 4*132+colv]=v1.x; Bs[ 5*132+colv]=v1.y; Bs[ 6*132+colv]=v1.z; Bs[ 7*132+colv]=v1.w;
            Bs[ 8*132+colv]=v2.x; Bs[ 9*132+colv]=v2.y; Bs[10*132+colv]=v2.z; Bs[11*132+colv]=v2.w;
            Bs[12*132+colv]=v3.x; Bs[13*132+colv]=v3.y; Bs[14*132+colv]=v3.z; Bs[15*132+colv]=v3.w;
        }
        __syncthreads();
#pragma unroll
        for (int k = 0; k < 16; k++) {
            uint64_t av[8], bv[4];
#pragma unroll
            for (int i = 0; i < 8; i++)
                av[i] = *(const uint64_t*)&As2[(ty*8+i)*32 + 2*k];
            bv[0] = *(const uint64_t*)&Bs[k*132 + tx*8 + 0];
            bv[1] = *(const uint64_t*)&Bs[k*132 + tx*8 + 2];
            bv[2] = *(const uint64_t*)&Bs[k*132 + tx*8 + 4];
            bv[3] = *(const uint64_t*)&Bs[k*132 + tx*8 + 6];
#pragma unroll
            for (int i = 0; i < 8; i++)
#pragma unroll
                for (int j = 0; j < 4; j++)
                    FMA_F32X2(acc[i][j], av[i], bv[j], acc[i][j]);
        }
        __syncthreads();
    }
#pragma unroll
    for (int i = 0; i < 8; i++) {
        int m = m0 + ty*8 + i;
        float bi = bias[m];
        float4 o0, o1;
        F2U u0, u1, u2, u3;
        u0.u = acc[i][0]; u1.u = acc[i][1]; u2.u = acc[i][2]; u3.u = acc[i][3];
        o0.x = u0.f.x+bi; o0.y = u0.f.y+bi; o0.z = u1.f.x+bi; o0.w = u1.f.y+bi;
        o1.x = u2.f.x+bi; o1.y = u2.f.y+bi; o1.z = u3.f.x+bi; o1.w = u3.f.y+bi;
        float* yp = g_Y0 + (size_t)m * NC + c0 + tx*8;
        *(float4*)yp = o0; *(float4*)(yp+4) = o1;
    }
}

// ---------------- GEMM1: out_raw[b][o][n] = W1 @ relu(bn0(Y0)) + b1 -------------
__global__ __launch_bounds__(256, 2) void gemm1_kernel(const float* __restrict__ A,
                                                       const float* __restrict__ bias,
                                                       float* __restrict__ out)
{
    __shared__ float As2[128*32];
    __shared__ float Bs[16*132];
    int t  = threadIdx.x;
    int c0 = blockIdx.x * 128;
    int tx = t & 15, ty = t >> 4;
    uint64_t acc[8][4];
#pragma unroll
    for (int i = 0; i < 8; i++)
#pragma unroll
        for (int j = 0; j < 4; j++) acc[i][j] = 0ull;

    for (int kk = 0; kk < CO0; kk += 16) {
        if (t < 128) {
            const float* ap = A + (size_t)t * CO0 + kk;
            float2* as = (float2*)&As2[t*32];
#pragma unroll
            for (int q = 0; q < 4; q++) {
                float4 v = *(const float4*)(ap + 4*q);
                as[4*q+0] = make_float2(v.x, v.x);
                as[4*q+1] = make_float2(v.y, v.y);
                as[4*q+2] = make_float2(v.z, v.z);
                as[4*q+3] = make_float2(v.w, v.w);
            }
        } else {
            int u = t - 128;
            int k = u >> 3;             // 0..15
            int colq = (u & 7) * 16;    // 0..112
            float sc = g_scale0[kk + k];
            float sh = g_shift0[kk + k];
            const float* yp = g_Y0 + (size_t)(kk + k) * NC + c0 + colq;
#pragma unroll
            for (int q = 0; q < 4; q++) {
                float4 v = *(const float4*)(yp + 4*q);
                v.x = fmaxf(0.f, fmaf(v.x, sc, sh));
                v.y = fmaxf(0.f, fmaf(v.y, sc, sh));
                v.z = fmaxf(0.f, fmaf(v.z, sc, sh));
                v.w = fmaxf(0.f, fmaf(v.w, sc, sh));
                *(float4*)&Bs[k*132 + colq + 4*q] = v;
            }
        }
        __syncthreads();
#pragma unroll
        for (int k = 0; k < 16; k++) {
            uint64_t av[8], bv[4];
#pragma unroll
            for (int i = 0; i < 8; i++)
                av[i] = *(const uint64_t*)&As2[(ty*8+i)*32 + 2*k];
            bv[0] = *(const uint64_t*)&Bs[k*132 + tx*8 + 0];
            bv[1] = *(const uint64_t*)&Bs[k*132 + tx*8 + 2];
            bv[2] = *(const uint64_t*)&Bs[k*132 + tx*8 + 4];
            bv[3] = *(const uint64_t*)&Bs[k*132 + tx*8 + 6];
#pragma unroll
            for (int i = 0; i < 8; i++)
#pragma unroll
                for (int j = 0; j < 4; j++)
                    FMA_F32X2(acc[i][j], av[i], bv[j], acc[i][j]);
        }
        __syncthreads();
    }
    int bidx  = c0 >> 13;          // batch (column tile never crosses batch)
    int nbase = c0 & (Nq - 1);
#pragma unroll
    for (int i = 0; i < 8; i++) {
        int m = ty*8 + i;
        float bi = bias[m];
        float4 o0, o1;
        F2U u0, u1, u2, u3;
        u0.u = acc[i][0]; u1.u = acc[i][1]; u2.u = acc[i][2]; u3.u = acc[i][3];
        o0.x = u0.f.x+bi; o0.y = u0.f.y+bi; o0.z = u1.f.x+bi; o0.w = u1.f.y+bi;
        o1.x = u2.f.x+bi; o1.y = u2.f.y+bi; o1.z = u3.f.x+bi; o1.w = u3.f.y+bi;
        float* op = out + (size_t)bidx * (CO1*Nq) + (size_t)m * Nq + nbase + tx*8;
        *(float4*)op = o0; *(float4*)(op+4) = o1;
    }
}

// ---------------- per-channel BN stats (deterministic, fp32 partials) -----------
__global__ __launch_bounds__(256) void stats_kernel(const float* __restrict__ Y,
    const float* __restrict__ g, const float* __restrict__ be,
    float* __restrict__ scale, float* __restrict__ shift,
    long long chan_stride, int nchunks, long long chunk_stride, int chunk_len, float inv_count)
{
    int o = blockIdx.x;
    int tid = threadIdx.x;
    float s = 0.f, q = 0.f;
    for (int cb = 0; cb < nchunks; cb++) {
        const float4* p = (const float4*)(Y + (size_t)o * chan_stride + (size_t)cb * chunk_stride);
        int len4 = chunk_len >> 2;
        for (int i = tid; i < len4; i += 256) {
            float4 v = p[i];
            s += (v.x + v.y) + (v.z + v.w);
            q += (v.x*v.x + v.y*v.y) + (v.z*v.z + v.w*v.w);
        }
    }
    __shared__ double ss[256], sq[256];
    ss[tid] = (double)s; sq[tid] = (double)q;
    __syncthreads();
    for (int st = 128; st > 0; st >>= 1) {
        if (tid < st) { ss[tid] += ss[tid+st]; sq[tid] += sq[tid+st]; }
        __syncthreads();
    }
    if (tid == 0) {
        double mean = ss[0] * (double)inv_count;
        double var  = sq[0] * (double)inv_count - mean*mean;
        double sc   = (double)g[o] / sqrt(var + 1e-5);
        scale[o] = (float)sc;
        shift[o] = (float)((double)be[o] - mean * sc);
    }
}

// ---------------- final BN + ReLU, in place on d_out ----------------------------
__global__ __launch_bounds__(256) void bnrelu_kernel(float* __restrict__ out)
{
    int i = blockIdx.x * 256 + threadIdx.x;   // float4 index; total 1048576
    int o = (i >> 11) & 127;
    float sc = g_scale1[o], sh = g_shift1[o];
    float4* p = (float4*)out;
    float4 v = p[i];
    v.x = fmaxf(0.f, fmaf(v.x, sc, sh));
    v.y = fmaxf(0.f, fmaf(v.y, sc, sh));
    v.z = fmaxf(0.f, fmaf(v.z, sc, sh));
    v.w = fmaxf(0.f, fmaf(v.w, sc, sh));
    p[i] = v;
}

// ---------------- launch ---------------------------------------------------------
extern "C" void kernel_launch(void* const* d_in, const int* in_sizes, int n_in,
                              void* d_out, int out_size)
{
    const float* xyz1    = (const float*)d_in[0];
    const float* xyz2    = (const float*)d_in[1];
    const float* norm1   = (const float*)d_in[2];
    const float* norm2   = (const float*)d_in[3];
    const float* points1 = (const float*)d_in[4];
    const float* points2 = (const float*)d_in[5];
    const float* W0      = (const float*)d_in[6];
    const float* b0      = (const float*)d_in[7];
    const float* g0      = (const float*)d_in[8];
    const float* be0     = (const float*)d_in[9];
    const float* W1      = (const float*)d_in[10];
    const float* b1      = (const float*)d_in[11];
    const float* g1      = (const float*)d_in[12];
    const float* be1     = (const float*)d_in[13];
    float* out = (float*)d_out;

    float *p2T_ptr, *X_ptr, *Y0_ptr, *sc0, *sh0, *sc1, *sh1;
    cudaGetSymbolAddress((void**)&p2T_ptr, g_p2T);
    cudaGetSymbolAddress((void**)&X_ptr,   g_X);
    cudaGetSymbolAddress((void**)&Y0_ptr,  g_Y0);
    cudaGetSymbolAddress((void**)&sc0, g_scale0);
    cudaGetSymbolAddress((void**)&sh0, g_shift0);
    cudaGetSymbolAddress((void**)&sc1, g_scale1);
    cudaGetSymbolAddress((void**)&sh1, g_shift1);

    // points2 (B,256,2048) -> g_p2T (B,2048,256)
    transpose_kernel<<<dim3(Mp/32, C2/32, Bsz), dim3(32,8)>>>(points2, p2T_ptr, C2, Mp, C2, 0);
    // points1 (B,128,8192) -> g_X[col][256..383]
    transpose_kernel<<<dim3(Nq/32, C1/32, Bsz), dim3(32,8)>>>(points1, X_ptr, C1, Nq, CIN, C2);
    // 3-NN + weights + interpolation -> g_X[col][0..255]
    knn_interp_kernel<<<dim3(Nq/128, Bsz), 128>>>(xyz1, xyz2, norm1, norm2);
    // conv0 raw
    gemm0_kernel<<<dim3(NC/128, CO0/128), 256>>>(W0, b0);
    // bn0 stats
    stats_kernel<<<CO0, 256>>>(Y0_ptr, g0, be0, sc0, sh0,
                               (long long)NC, 1, 0LL, NC, 1.0f/(float)NC);
    // conv1 raw (bn0 + relu fused on load), write raw to d_out
    gemm1_kernel<<<dim3(NC/128, 1), 256>>>(W1, b1, out);
    // bn1 stats over d_out raw
    stats_kernel<<<CO1, 256>>>(out, g1, be1, sc1, sh1,
                               (long long)Nq, Bsz, (long long)(CO1*Nq), Nq, 1.0f/(float)NC);
    // final bn1 + relu, in place
    bnrelu_kernel<<<(Bsz*CO1*Nq/4)/256, 256>>>(out);
}

// round 8
// speedup vs baseline: 1.8331x; 1.8331x over previous
#include <cuda_runtime.h>
#include <cuda_bf16.h>
#include <math.h>
#include <stdint.h>

#define Bsz 4
#define Nq  8192
#define Mp  2048
#define C1  128
#define C2  256
#define CIN 384
#define CO0 256
#define CO1 128
#define NC  (Bsz*Nq)   // 32768

// ---------------- scratch (static device globals; no allocation) ----------------
__device__ float g_p2T[Bsz*Mp*C2];                       // points2^T (B,M,C2) fp32
__device__ __nv_bfloat16 g_Xhi[(size_t)NC*CIN];          // X hi split [col][k]
__device__ __nv_bfloat16 g_Xlo[(size_t)NC*CIN];          // X lo split [col][k]
__device__ __nv_bfloat16 g_W0h[CO0*CIN], g_W0l[CO0*CIN];
__device__ __nv_bfloat16 g_W1h[CO1*CO0], g_W1l[CO1*CO0];
__device__ float g_Y0T[(size_t)NC*CO0];                  // conv0 out [pt][ch] fp32
__device__ float g_p0s[512*CO0], g_p0q[512*CO0];         // bn0 partials
__device__ float g_scale0[CO0], g_shift0[CO0];
__device__ float g_scale1[CO1], g_shift1[CO1];

// ---------------- helpers --------------------------------------------------------
__device__ __forceinline__ uint32_t smem_u32(const void* p) {
    uint32_t a;
    asm("{ .reg .u64 t; cvta.to.shared.u64 t, %1; cvt.u32.u64 %0, t; }" : "=r"(a) : "l"(p));
    return a;
}

#define LDSM4(r, addr) \
    asm volatile("ldmatrix.sync.aligned.m8n8.x4.shared.b16 {%0,%1,%2,%3}, [%4];" \
        : "=r"((r)[0]),"=r"((r)[1]),"=r"((r)[2]),"=r"((r)[3]) : "r"(addr))

__device__ __forceinline__ void mma_bf16(float* d, const uint32_t* a, const uint32_t* b) {
    asm volatile("mma.sync.aligned.m16n8k16.row.col.f32.bf16.bf16.f32 "
        "{%0,%1,%2,%3}, {%4,%5,%6,%7}, {%8,%9}, {%0,%1,%2,%3};"
        : "+f"(d[0]), "+f"(d[1]), "+f"(d[2]), "+f"(d[3])
        : "r"(a[0]), "r"(a[1]), "r"(a[2]), "r"(a[3]), "r"(b[0]), "r"(b[1]));
}

__device__ __forceinline__ void split_bf(float v, unsigned short& h, unsigned short& l) {
    __nv_bfloat16 hb = __float2bfloat16(v);
    float hf = __bfloat162float(hb);
    __nv_bfloat16 lb = __float2bfloat16(v - hf);
    union { __nv_bfloat16 b; unsigned short u; } ch, cl;
    ch.b = hb; cl.b = lb;
    h = ch.u; l = cl.u;
}

// split 8 fp32 -> packed uint4 hi / uint4 lo (8 bf16 each)
__device__ __forceinline__ void split8(const float* v, uint4& h4, uint4& l4) {
    unsigned short h[8], l[8];
#pragma unroll
    for (int i = 0; i < 8; i++) split_bf(v[i], h[i], l[i]);
    h4 = make_uint4((uint32_t)h[0]|((uint32_t)h[1]<<16), (uint32_t)h[2]|((uint32_t)h[3]<<16),
                    (uint32_t)h[4]|((uint32_t)h[5]<<16), (uint32_t)h[6]|((uint32_t)h[7]<<16));
    l4 = make_uint4((uint32_t)l[0]|((uint32_t)l[1]<<16), (uint32_t)l[2]|((uint32_t)l[3]<<16),
                    (uint32_t)l[4]|((uint32_t)l[5]<<16), (uint32_t)l[6]|((uint32_t)l[7]<<16));
}

// ---------------- weight presplit ------------------------------------------------
__global__ void splitw_kernel(const float* __restrict__ W0, const float* __restrict__ W1)
{
    int i = blockIdx.x * 256 + threadIdx.x;
    if (i < CO0*CIN) {
        unsigned short h, l; split_bf(W0[i], h, l);
        union { __nv_bfloat16 b; unsigned short u; } ch, cl; ch.u = h; cl.u = l;
        g_W0h[i] = ch.b; g_W0l[i] = cl.b;
    }
    int j = i - CO0*CIN;
    if (j >= 0 && j < CO1*CO0) {
        unsigned short h, l; split_bf(W1[j], h, l);
        union { __nv_bfloat16 b; unsigned short u; } ch, cl; ch.u = h; cl.u = l;
        g_W1h[j] = ch.b; g_W1l[j] = cl.b;
    }
}

// ---------------- transpose (fp32): in (B,R,C) -> out[(b*C+c)*ostride + r] -------
__global__ void transpose_kernel(const float* __restrict__ in, float* __restrict__ out,
                                 int R, int C, int ostride)
{
    __shared__ float tile[32][33];
    int b  = blockIdx.z;
    int c0 = blockIdx.x * 32;
    int r0 = blockIdx.y * 32;
    const float* ip = in + (size_t)b * R * C;
#pragma unroll
    for (int s = 0; s < 4; s++) {
        int r = r0 + threadIdx.y + 8*s;
        tile[threadIdx.y + 8*s][threadIdx.x] = ip[(size_t)r * C + c0 + threadIdx.x];
    }
    __syncthreads();
#pragma unroll
    for (int s = 0; s < 4; s++) {
        int c = c0 + threadIdx.y + 8*s;
        out[((size_t)b * C + c) * ostride + r0 + threadIdx.x] = tile[threadIdx.x][threadIdx.y + 8*s];
    }
}

// ---------------- transpose points1 -> split bf16 into g_Xhi/lo [col][256+r] ----
__global__ void transpose_split_kernel(const float* __restrict__ in)
{
    __shared__ float tile[32][33];
    int b  = blockIdx.z;
    int c0 = blockIdx.x * 32;   // point
    int r0 = blockIdx.y * 32;   // channel
    const float* ip = in + (size_t)b * C1 * Nq;
#pragma unroll
    for (int s = 0; s < 4; s++) {
        int r = r0 + threadIdx.y + 8*s;
        tile[threadIdx.y + 8*s][threadIdx.x] = ip[(size_t)r * Nq + c0 + threadIdx.x];
    }
    __syncthreads();
#pragma unroll
    for (int s = 0; s < 4; s++) {
        int c = c0 + threadIdx.y + 8*s;
        float v = tile[threadIdx.x][threadIdx.y + 8*s];
        unsigned short h, l;
        split_bf(v, h, l);
        size_t idx = ((size_t)b * Nq + c) * CIN + C2 + r0 + threadIdx.x;
        union { __nv_bfloat16 b16; unsigned short u; } cvh, cvl;
        cvh.u = h; cvl.u = l;
        g_Xhi[idx] = cvh.b16;
        g_Xlo[idx] = cvl.b16;
    }
}

// ---------------- 3-NN + weights + interpolation -> g_Xhi/lo[col][0..255] -------
__global__ __launch_bounds__(128) void knn_interp_kernel(
    const float* __restrict__ xyz1, const float* __restrict__ xyz2,
    const float* __restrict__ norm1, const float* __restrict__ norm2)
{
    __shared__ float4 sp[Mp];
    int b = blockIdx.y;
    const float* x2 = xyz2 + (size_t)b * 3 * Mp;
    for (int m = threadIdx.x; m < Mp; m += 128) {
        float a = x2[m], c = x2[Mp + m], d = x2[2*Mp + m];
        float4 v; v.x = a; v.y = c; v.z = d; v.w = a*a + c*c + d*d;
        sp[m] = v;
    }
    __syncthreads();

    int n = blockIdx.x * 128 + threadIdx.x;
    const float* x1 = xyz1 + (size_t)b * 3 * Nq;
    float qx = x1[n], qy = x1[Nq + n], qz = x1[2*Nq + n];
    float qq = qx*qx + qy*qy + qz*qz;

    float d2_0 = 1e30f, d2_1 = 1e30f, d2_2 = 1e30f;
    int   i0 = 0, i1 = 0, i2 = 0;
#pragma unroll 4
    for (int m = 0; m < Mp; m++) {
        float4 P = sp[m];
        float dot = qx*P.x + qy*P.y + qz*P.z;
        float d2  = qq + P.w - 2.0f*dot;
        if (d2 < d2_2) {
            if (d2 < d2_1) {
                d2_2 = d2_1; i2 = i1;
                if (d2 < d2_0) { d2_1 = d2_0; i1 = i0; d2_0 = d2; i0 = m; }
                else           { d2_1 = d2;  i1 = m; }
            } else { d2_2 = d2; i2 = m; }
        }
    }
    float dist0 = sqrtf(fmaxf(d2_0, 1e-20f));
    float dist1 = sqrtf(fmaxf(d2_1, 1e-20f));
    float dist2 = sqrtf(fmaxf(d2_2, 1e-20f));

    const float* n1 = norm1 + (size_t)b * 3 * Nq;
    const float* n2 = norm2 + (size_t)b * 3 * Mp;
    float ax = n1[n], ay = n1[Nq+n], az = n1[2*Nq+n];
    float dx, dy, dz;
    dx = ax - n2[i0]; dy = ay - n2[Mp+i0]; dz = az - n2[2*Mp+i0];
    float nd0 = sqrtf(dx*dx + dy*dy + dz*dz);
    dx = ax - n2[i1]; dy = ay - n2[Mp+i1]; dz = az - n2[2*Mp+i1];
    float nd1 = sqrtf(dx*dx + dy*dy + dz*dz);
    dx = ax - n2[i2]; dy = ay - n2[Mp+i2]; dz = az - n2[2*Mp+i2];
    float nd2 = sqrtf(dx*dx + dy*dy + dz*dz);

    float r0 = 1.0f / fmaxf(dist0, 1e-10f);
    float r1 = 1.0f / fmaxf(dist1, 1e-10f);
    float r2 = 1.0f / fmaxf(dist2, 1e-10f);
    float rs = r0 + r1 + r2;
    float s0 = 1.0f / fmaxf(nd0, 1e-10f);
    float s1 = 1.0f / fmaxf(nd1, 1e-10f);
    float s2 = 1.0f / fmaxf(nd2, 1e-10f);
    float ssum = s0 + s1 + s2;
    float w0 = (r0 / rs) * (s0 / ssum);
    float w1 = (r1 / rs) * (s1 / ssum);
    float w2 = (r2 / rs) * (s2 / ssum);

    size_t col = (size_t)b * Nq + n;
    const float4* p0 = (const float4*)(g_p2T + ((size_t)b*Mp + i0) * C2);
    const float4* p1 = (const float4*)(g_p2T + ((size_t)b*Mp + i1) * C2);
    const float4* p2 = (const float4*)(g_p2T + ((size_t)b*Mp + i2) * C2);
    uint2* xh = (uint2*)(g_Xhi + col * CIN);
    uint2* xl = (uint2*)(g_Xlo + col * CIN);
#pragma unroll 4
    for (int c = 0; c < C2/4; c++) {
        float4 a = p0[c], bq = p1[c], cq = p2[c];
        float r[4];
        r[0] = w0*a.x + w1*bq.x + w2*cq.x;
        r[1] = w0*a.y + w1*bq.y + w2*cq.y;
        r[2] = w0*a.z + w1*bq.z + w2*cq.z;
        r[3] = w0*a.w + w1*bq.w + w2*cq.w;
        unsigned short h[4], l[4];
#pragma unroll
        for (int j = 0; j < 4; j++) split_bf(r[j], h[j], l[j]);
        xh[c] = make_uint2((uint32_t)h[0] | ((uint32_t)h[1]<<16),
                           (uint32_t)h[2] | ((uint32_t)h[3]<<16));
        xl[c] = make_uint2((uint32_t)l[0] | ((uint32_t)l[1]<<16),
                           (uint32_t)l[2] | ((uint32_t)l[3]<<16));
    }
}

// ---------------- GEMM0 (mma.sync bf16x3): D[ch 128][pt 128] --------------------
// smem: staging 4x16KB swizzled bf16 tiles; epilogue reuses as fp32 [pt][132]
#define SMA_H 0
#define SMA_L 16384
#define SMB_H 32768
#define SMB_L 49152
#define G0_SMEM (128*132*4)     // 67584

__global__ __launch_bounds__(256, 1) void gemm0_mma_kernel(const float* __restrict__ bias)
{
    extern __shared__ char sm[];
    uint32_t smb = smem_u32(sm);
    int t = threadIdx.x, lid = t & 31, wid = t >> 5;
    int wm = wid >> 2, wn = wid & 3;          // warps 2(m) x 4(n)
    int c0 = blockIdx.x * 128;                // point tile
    int m0 = blockIdx.y * 128;                // channel tile
    int sub = lid >> 3, rr = lid & 7;

    float acc[4][4][4];
#pragma unroll
    for (int i = 0; i < 4; i++)
#pragma unroll
        for (int j = 0; j < 4; j++)
#pragma unroll
            for (int q = 0; q < 4; q++) acc[i][j][q] = 0.f;

    for (int ck = 0; ck < 6; ck++) {
        int kk = ck * 64;
        __syncthreads();
        for (int i = t; i < 128*8; i += 256) {
            int r = i >> 3, j = i & 7;
            uint32_t so = (uint32_t)(r*128 + ((j ^ (r & 7)) << 4));
            *(uint4*)(sm + SMA_H + so) = *(const uint4*)(g_W0h + (size_t)(m0 + r)*CIN + kk + j*8);
            *(uint4*)(sm + SMA_L + so) = *(const uint4*)(g_W0l + (size_t)(m0 + r)*CIN + kk + j*8);
            *(uint4*)(sm + SMB_H + so) = *(const uint4*)(g_Xhi + (size_t)(c0 + r)*CIN + kk + j*8);
            *(uint4*)(sm + SMB_L + so) = *(const uint4*)(g_Xlo + (size_t)(c0 + r)*CIN + kk + j*8);
        }
        __syncthreads();
#pragma unroll
        for (int kb = 0; kb < 4; kb++) {
            int chnk = kb*2 + (sub >> 1);
            uint32_t Ah[4][4], Al[4][4], Bh[4][2], Bl[4][2];
#pragma unroll
            for (int i = 0; i < 4; i++) {
                int row = wm*64 + i*16 + ((sub & 1) << 3) + rr;
                uint32_t so = (uint32_t)(row*128 + ((chnk ^ rr) << 4));
                LDSM4(Ah[i], smb + SMA_H + so);
                LDSM4(Al[i], smb + SMA_L + so);
            }
#pragma unroll
            for (int jj = 0; jj < 2; jj++) {
                int row = wn*32 + jj*16 + ((sub & 1) << 3) + rr;
                uint32_t so = (uint32_t)(row*128 + ((chnk ^ rr) << 4));
                uint32_t rg[4];
                LDSM4(rg, smb + SMB_H + so);
                Bh[jj*2][0] = rg[0]; Bh[jj*2+1][0] = rg[1];
                Bh[jj*2][1] = rg[2]; Bh[jj*2+1][1] = rg[3];
                LDSM4(rg, smb + SMB_L + so);
                Bl[jj*2][0] = rg[0]; Bl[jj*2+1][0] = rg[1];
                Bl[jj*2][1] = rg[2]; Bl[jj*2+1][1] = rg[3];
            }
#pragma unroll
            for (int i = 0; i < 4; i++)
#pragma unroll
                for (int jt = 0; jt < 4; jt++) {
                    mma_bf16(acc[i][jt], Ah[i], Bh[jt]);
                    mma_bf16(acc[i][jt], Ah[i], Bl[jt]);
                    mma_bf16(acc[i][jt], Al[i], Bh[jt]);
                }
        }
    }

    // epilogue: transpose through smem -> g_Y0T [pt][ch], bn0 partials
    __syncthreads();
    float* s32 = (float*)sm;
#pragma unroll
    for (int i = 0; i < 4; i++) {
        int chr = wm*64 + i*16 + (lid >> 2);
#pragma unroll
        for (int jt = 0; jt < 4; jt++) {
            int pt = wn*32 + jt*8 + (lid & 3)*2;
            s32[(size_t)pt*132 + chr]       = acc[i][jt][0];
            s32[(size_t)(pt+1)*132 + chr]   = acc[i][jt][1];
            s32[(size_t)pt*132 + chr + 8]   = acc[i][jt][2];
            s32[(size_t)(pt+1)*132 + chr+8] = acc[i][jt][3];
        }
    }
    __syncthreads();
    int chn = t & 127, half = t >> 7;
    float bi = bias[m0 + chn];
    float s = 0.f, q = 0.f;
    for (int p = half*64; p < half*64 + 64; p++) {
        float v = s32[(size_t)p*132 + chn] + bi;
        s += v; q += v*v;
        g_Y0T[(size_t)(c0 + p)*CO0 + m0 + chn] = v;
    }
    g_p0s[(size_t)(blockIdx.x*2 + half)*CO0 + m0 + chn] = s;
    g_p0q[(size_t)(blockIdx.x*2 + half)*CO0 + m0 + chn] = q;
}

// ---------------- bn0 partial reduce -> scale0/shift0 ---------------------------
__global__ __launch_bounds__(256) void reduce0_kernel(const float* __restrict__ g,
                                                      const float* __restrict__ be)
{
    int chn = blockIdx.x, t = threadIdx.x;
    double s = (double)g_p0s[(size_t)t*CO0 + chn] + (double)g_p0s[(size_t)(t+256)*CO0 + chn];
    double q = (double)g_p0q[(size_t)t*CO0 + chn] + (double)g_p0q[(size_t)(t+256)*CO0 + chn];
    __shared__ double ss[256], qq[256];
    ss[t] = s; qq[t] = q;
    __syncthreads();
    for (int st = 128; st > 0; st >>= 1) {
        if (t < st) { ss[t] += ss[t+st]; qq[t] += qq[t+st]; }
        __syncthreads();
    }
    if (t == 0) {
        double inv = 1.0 / (double)NC;
        double mean = ss[0] * inv;
        double var  = qq[0] * inv - mean*mean;
        double sc   = (double)g[chn] / sqrt(var + 1e-5);
        g_scale0[chn] = (float)sc;
        g_shift0[chn] = (float)((double)be[chn] - mean * sc);
    }
}

// ---------------- GEMM1 (mma.sync bf16x3): D[ch 128][pt 128] -> d_out -----------
#define G1_SMEM (65536 + 2048)

__global__ __launch_bounds__(256, 1) void gemm1_mma_kernel(const float* __restrict__ bias,
                                                           float* __restrict__ out)
{
    extern __shared__ char sm[];
    uint32_t smb = smem_u32(sm);
    float* s_sc = (float*)(sm + 65536);
    float* s_sh = (float*)(sm + 65536 + 1024);
    int t = threadIdx.x, lid = t & 31, wid = t >> 5;
    int wm = wid >> 2, wn = wid & 3;
    int p0 = blockIdx.x * 128;
    int sub = lid >> 3, rr = lid & 7;

    s_sc[t] = g_scale0[t];
    s_sh[t] = g_shift0[t];

    float acc[4][4][4];
#pragma unroll
    for (int i = 0; i < 4; i++)
#pragma unroll
        for (int j = 0; j < 4; j++)
#pragma unroll
            for (int q = 0; q < 4; q++) acc[i][j][q] = 0.f;

    for (int ck = 0; ck < 4; ck++) {
        int kk = ck * 64;
        __syncthreads();
        for (int i = t; i < 128*8; i += 256) {
            int r = i >> 3, j = i & 7;
            uint32_t so = (uint32_t)(r*128 + ((j ^ (r & 7)) << 4));
            *(uint4*)(sm + SMA_H + so) = *(const uint4*)(g_W1h + (size_t)r*CO0 + kk + j*8);
            *(uint4*)(sm + SMA_L + so) = *(const uint4*)(g_W1l + (size_t)r*CO0 + kk + j*8);
            // B: Y0T + bn0 + relu -> split
            const float* yp = g_Y0T + (size_t)(p0 + r)*CO0 + kk + j*8;
            float v[8];
#pragma unroll
            for (int q = 0; q < 8; q++) {
                int k = kk + j*8 + q;
                v[q] = fmaxf(0.f, fmaf(yp[q], s_sc[k], s_sh[k]));
            }
            uint4 h4, l4;
            split8(v, h4, l4);
            *(uint4*)(sm + SMB_H + so) = h4;
            *(uint4*)(sm + SMB_L + so) = l4;
        }
        __syncthreads();
#pragma unroll
        for (int kb = 0; kb < 4; kb++) {
            int chnk = kb*2 + (sub >> 1);
            uint32_t Ah[4][4], Al[4][4], Bh[4][2], Bl[4][2];
#pragma unroll
            for (int i = 0; i < 4; i++) {
                int row = wm*64 + i*16 + ((sub & 1) << 3) + rr;
                uint32_t so = (uint32_t)(row*128 + ((chnk ^ rr) << 4));
                LDSM4(Ah[i], smb + SMA_H + so);
                LDSM4(Al[i], smb + SMA_L + so);
            }
#pragma unroll
            for (int jj = 0; jj < 2; jj++) {
                int row = wn*32 + jj*16 + ((sub & 1) << 3) + rr;
                uint32_t so = (uint32_t)(row*128 + ((chnk ^ rr) << 4));
                uint32_t rg[4];
                LDSM4(rg, smb + SMB_H + so);
                Bh[jj*2][0] = rg[0]; Bh[jj*2+1][0] = rg[1];
                Bh[jj*2][1] = rg[2]; Bh[jj*2+1][1] = rg[3];
                LDSM4(rg, smb + SMB_L + so);
                Bl[jj*2][0] = rg[0]; Bl[jj*2+1][0] = rg[1];
                Bl[jj*2][1] = rg[2]; Bl[jj*2+1][1] = rg[3];
            }
#pragma unroll
            for (int i = 0; i < 4; i++)
#pragma unroll
                for (int jt = 0; jt < 4; jt++) {
                    mma_bf16(acc[i][jt], Ah[i], Bh[jt]);
                    mma_bf16(acc[i][jt], Ah[i], Bl[jt]);
                    mma_bf16(acc[i][jt], Al[i], Bh[jt]);
                }
        }
    }

    // epilogue: direct to out[b][ch][n] (n-contiguous float2 stores)
#pragma unroll
    for (int i = 0; i < 4; i++) {
        int ch = wm*64 + i*16 + (lid >> 2);
        float b0v = bias[ch], b8v = bias[ch + 8];
#pragma unroll
        for (int jt = 0; jt < 4; jt++) {
            int ptl = wn*32 + jt*8 + (lid & 3)*2;
            int gp = p0 + ptl;
            int b = gp >> 13, n = gp & (Nq - 1);
            float2 v0 = make_float2(acc[i][jt][0] + b0v, acc[i][jt][1] + b0v);
            float2 v1 = make_float2(acc[i][jt][2] + b8v, acc[i][jt][3] + b8v);
            *(float2*)(out + ((size_t)b*CO1 + ch)*Nq + n)     = v0;
            *(float2*)(out + ((size_t)b*CO1 + ch + 8)*Nq + n) = v1;
        }
    }
}

// ---------------- per-channel BN stats (bn1 over d_out) -------------------------
__global__ __launch_bounds__(256) void stats_kernel(const float* __restrict__ Y,
    const float* __restrict__ g, const float* __restrict__ be,
    float* __restrict__ scale, float* __restrict__ shift,
    long long chan_stride, int nchunks, long long chunk_stride, int chunk_len, float inv_count)
{
    int o = blockIdx.x;
    int tid = threadIdx.x;
    float s = 0.f, q = 0.f;
    for (int cb = 0; cb < nchunks; cb++) {
        const float4* p = (const float4*)(Y + (size_t)o * chan_stride + (size_t)cb * chunk_stride);
        int len4 = chunk_len >> 2;
        for (int i = tid; i < len4; i += 256) {
            float4 v = p[i];
            s += (v.x + v.y) + (v.z + v.w);
            q += (v.x*v.x + v.y*v.y) + (v.z*v.z + v.w*v.w);
        }
    }
    __shared__ double ss[256], sq[256];
    ss[tid] = (double)s; sq[tid] = (double)q;
    __syncthreads();
    for (int st = 128; st > 0; st >>= 1) {
        if (tid < st) { ss[tid] += ss[tid+st]; sq[tid] += sq[tid+st]; }
        __syncthreads();
    }
    if (tid == 0) {
        double mean = ss[0] * (double)inv_count;
        double var  = sq[0] * (double)inv_count - mean*mean;
        double sc   = (double)g[o] / sqrt(var + 1e-5);
        scale[o] = (float)sc;
        shift[o] = (float)((double)be[o] - mean * sc);
    }
}

// ---------------- final BN + ReLU, in place on d_out ----------------------------
__global__ __launch_bounds__(256) void bnrelu_kernel(float* __restrict__ out)
{
    int i = blockIdx.x * 256 + threadIdx.x;
    int o = (i >> 11) & 127;
    float sc = g_scale1[o], sh = g_shift1[o];
    float4* p = (float4*)out;
    float4 v = p[i];
    v.x = fmaxf(0.f, fmaf(v.x, sc, sh));
    v.y = fmaxf(0.f, fmaf(v.y, sc, sh));
    v.z = fmaxf(0.f, fmaf(v.z, sc, sh));
    v.w = fmaxf(0.f, fmaf(v.w, sc, sh));
    p[i] = v;
}

// ---------------- launch ---------------------------------------------------------
extern "C" void kernel_launch(void* const* d_in, const int* in_sizes, int n_in,
                              void* d_out, int out_size)
{
    const float* xyz1    = (const float*)d_in[0];
    const float* xyz2    = (const float*)d_in[1];
    const float* norm1   = (const float*)d_in[2];
    const float* norm2   = (const float*)d_in[3];
    const float* points1 = (const float*)d_in[4];
    const float* points2 = (const float*)d_in[5];
    const float* W0      = (const float*)d_in[6];
    const float* b0      = (const float*)d_in[7];
    const float* g0      = (const float*)d_in[8];
    const float* be0     = (const float*)d_in[9];
    const float* W1      = (const float*)d_in[10];
    const float* b1      = (const float*)d_in[11];
    const float* g1      = (const float*)d_in[12];
    const float* be1     = (const float*)d_in[13];
    float* out = (float*)d_out;

    cudaFuncSetAttribute(gemm0_mma_kernel, cudaFuncAttributeMaxDynamicSharedMemorySize, G0_SMEM);
    cudaFuncSetAttribute(gemm1_mma_kernel, cudaFuncAttributeMaxDynamicSharedMemorySize, G1_SMEM);

    float *p2T_ptr, *sc1, *sh1;
    cudaGetSymbolAddress((void**)&p2T_ptr, g_p2T);
    cudaGetSymbolAddress((void**)&sc1, g_scale1);
    cudaGetSymbolAddress((void**)&sh1, g_shift1);

    // weight presplit (bf16 hi/lo)
    splitw_kernel<<<(CO0*CIN + CO1*CO0 + 255)/256, 256>>>(W0, W1);
    // points2 (B,256,2048) -> g_p2T (B,2048,256) fp32
    transpose_kernel<<<dim3(Mp/32, C2/32, Bsz), dim3(32,8)>>>(points2, p2T_ptr, C2, Mp, C2);
    // points1 -> split bf16 into g_Xhi/lo [col][256..383]
    transpose_split_kernel<<<dim3(Nq/32, C1/32, Bsz), dim3(32,8)>>>(points1);
    // 3-NN + interpolation -> g_Xhi/lo [col][0..255]
    knn_interp_kernel<<<dim3(Nq/128, Bsz), 128>>>(xyz1, xyz2, norm1, norm2);
    // conv0 (HMMA bf16x3) -> g_Y0T [pt][ch] + bn0 partials
    gemm0_mma_kernel<<<dim3(NC/128, CO0/128), 256, G0_SMEM>>>(b0);
    // bn0 affine
    reduce0_kernel<<<CO0, 256>>>(g0, be0);
    // conv1 (HMMA bf16x3, bn0+relu fused in staging) -> d_out raw
    gemm1_mma_kernel<<<dim3(NC/128), 256, G1_SMEM>>>(b1, out);
    // bn1 stats over d_out raw
    stats_kernel<<<CO1, 256>>>(out, g1, be1, sc1, sh1,
                               (long long)Nq, Bsz, (long long)(CO1*Nq), Nq, 1.0f/(float)NC);
    // final bn1 + relu in place
    bnrelu_kernel<<<(Bsz*CO1*Nq/4)/256, 256>>>(out);
}

// round 9
// speedup vs baseline: 2.1610x; 1.1788x over previous
#include <cuda_runtime.h>
#include <cuda_bf16.h>
#include <math.h>
#include <stdint.h>

#define Bsz 4
#define Nq  8192
#define Mp  2048
#define C1  128
#define C2  256
#define CIN 384
#define CO0 256
#define CO1 128
#define NC  (Bsz*Nq)   // 32768

// ---------------- scratch (static device globals; no allocation) ----------------
__device__ float g_p2T[Bsz*Mp*C2];                       // points2^T (B,M,C2) fp32
__device__ __nv_bfloat16 g_Xhi[(size_t)NC*CIN];          // X hi split [col][k]
__device__ __nv_bfloat16 g_Xlo[(size_t)NC*CIN];          // X lo split [col][k]
__device__ __nv_bfloat16 g_W0h[CO0*CIN], g_W0l[CO0*CIN];
__device__ __nv_bfloat16 g_W1h[CO1*CO0], g_W1l[CO1*CO0];
__device__ float g_Y0T[(size_t)NC*CO0];                  // conv0 out [pt][ch] fp32
__device__ float g_p0s[512*CO0], g_p0q[512*CO0];         // bn0 partials
__device__ float g_scale0[CO0], g_shift0[CO0];
__device__ float g_scale1[CO1], g_shift1[CO1];

// ---------------- helpers --------------------------------------------------------
__device__ __forceinline__ uint32_t smem_u32(const void* p) {
    uint32_t a;
    asm("{ .reg .u64 t; cvta.to.shared.u64 t, %1; cvt.u32.u64 %0, t; }" : "=r"(a) : "l"(p));
    return a;
}

#define LDSM4(r, addr) \
    asm volatile("ldmatrix.sync.aligned.m8n8.x4.shared.b16 {%0,%1,%2,%3}, [%4];" \
        : "=r"((r)[0]),"=r"((r)[1]),"=r"((r)[2]),"=r"((r)[3]) : "r"(addr))

__device__ __forceinline__ void mma_bf16(float* d, const uint32_t* a, const uint32_t* b) {
    asm volatile("mma.sync.aligned.m16n8k16.row.col.f32.bf16.bf16.f32 "
        "{%0,%1,%2,%3}, {%4,%5,%6,%7}, {%8,%9}, {%0,%1,%2,%3};"
        : "+f"(d[0]), "+f"(d[1]), "+f"(d[2]), "+f"(d[3])
        : "r"(a[0]), "r"(a[1]), "r"(a[2]), "r"(a[3]), "r"(b[0]), "r"(b[1]));
}

__device__ __forceinline__ void split_bf(float v, unsigned short& h, unsigned short& l) {
    __nv_bfloat16 hb = __float2bfloat16(v);
    float hf = __bfloat162float(hb);
    __nv_bfloat16 lb = __float2bfloat16(v - hf);
    union { __nv_bfloat16 b; unsigned short u; } ch, cl;
    ch.b = hb; cl.b = lb;
    h = ch.u; l = cl.u;
}

__device__ __forceinline__ void split8(const float* v, uint4& h4, uint4& l4) {
    unsigned short h[8], l[8];
#pragma unroll
    for (int i = 0; i < 8; i++) split_bf(v[i], h[i], l[i]);
    h4 = make_uint4((uint32_t)h[0]|((uint32_t)h[1]<<16), (uint32_t)h[2]|((uint32_t)h[3]<<16),
                    (uint32_t)h[4]|((uint32_t)h[5]<<16), (uint32_t)h[6]|((uint32_t)h[7]<<16));
    l4 = make_uint4((uint32_t)l[0]|((uint32_t)l[1]<<16), (uint32_t)l[2]|((uint32_t)l[3]<<16),
                    (uint32_t)l[4]|((uint32_t)l[5]<<16), (uint32_t)l[6]|((uint32_t)l[7]<<16));
}

// ---------------- weight presplit ------------------------------------------------
__global__ void splitw_kernel(const float* __restrict__ W0, const float* __restrict__ W1)
{
    int i = blockIdx.x * 256 + threadIdx.x;
    if (i < CO0*CIN) {
        unsigned short h, l; split_bf(W0[i], h, l);
        union { __nv_bfloat16 b; unsigned short u; } ch, cl; ch.u = h; cl.u = l;
        g_W0h[i] = ch.b; g_W0l[i] = cl.b;
    }
    int j = i - CO0*CIN;
    if (j >= 0 && j < CO1*CO0) {
        unsigned short h, l; split_bf(W1[j], h, l);
        union { __nv_bfloat16 b; unsigned short u; } ch, cl; ch.u = h; cl.u = l;
        g_W1h[j] = ch.b; g_W1l[j] = cl.b;
    }
}

// ---------------- transpose (fp32): in (B,R,C) -> out[(b*C+c)*ostride + r] -------
__global__ void transpose_kernel(const float* __restrict__ in, float* __restrict__ out,
                                 int R, int C, int ostride)
{
    __shared__ float tile[32][33];
    int b  = blockIdx.z;
    int c0 = blockIdx.x * 32;
    int r0 = blockIdx.y * 32;
    const float* ip = in + (size_t)b * R * C;
#pragma unroll
    for (int s = 0; s < 4; s++) {
        int r = r0 + threadIdx.y + 8*s;
        tile[threadIdx.y + 8*s][threadIdx.x] = ip[(size_t)r * C + c0 + threadIdx.x];
    }
    __syncthreads();
#pragma unroll
    for (int s = 0; s < 4; s++) {
        int c = c0 + threadIdx.y + 8*s;
        out[((size_t)b * C + c) * ostride + r0 + threadIdx.x] = tile[threadIdx.x][threadIdx.y + 8*s];
    }
}

// ---------------- transpose points1 -> split bf16 into g_Xhi/lo [col][256+r] ----
__global__ void transpose_split_kernel(const float* __restrict__ in)
{
    __shared__ float tile[32][33];
    int b  = blockIdx.z;
    int c0 = blockIdx.x * 32;   // point
    int r0 = blockIdx.y * 32;   // channel
    const float* ip = in + (size_t)b * C1 * Nq;
#pragma unroll
    for (int s = 0; s < 4; s++) {
        int r = r0 + threadIdx.y + 8*s;
        tile[threadIdx.y + 8*s][threadIdx.x] = ip[(size_t)r * Nq + c0 + threadIdx.x];
    }
    __syncthreads();
#pragma unroll
    for (int s = 0; s < 4; s++) {
        int c = c0 + threadIdx.y + 8*s;
        float v = tile[threadIdx.x][threadIdx.y + 8*s];
        unsigned short h, l;
        split_bf(v, h, l);
        size_t idx = ((size_t)b * Nq + c) * CIN + C2 + r0 + threadIdx.x;
        union { __nv_bfloat16 b16; unsigned short u; } cvh, cvl;
        cvh.u = h; cvl.u = l;
        g_Xhi[idx] = cvh.b16;
        g_Xlo[idx] = cvl.b16;
    }
}

// ---------------- 3-NN + weights + interpolation (chunked scan, 512 thr) --------
// Each block: 128 queries. 4 chunks of 512 refs scanned by 4 thread groups,
// per-chunk top-3 merged in chunk-then-rank order (strict < preserves the
// global scan's tie semantics). Gather spread across all 512 threads.
#define KCH 4
#define KCHLEN (Mp/KCH)   // 512

__global__ __launch_bounds__(512) void knn_interp_kernel(
    const float* __restrict__ xyz1, const float* __restrict__ xyz2,
    const float* __restrict__ norm1, const float* __restrict__ norm2)
{
    __shared__ float4 sp[Mp];             // 32 KB
    __shared__ float  cd[12][128];        // 6 KB  [chunk*3+rank][query]
    __shared__ int    ci[12][128];        // 6 KB
    __shared__ float  sw[3][128];         // weights
    __shared__ int    si[3][128];         // indices

    int b = blockIdx.y;
    int t = threadIdx.x;
    int qi = t & 127, c = t >> 7;

    const float* x2 = xyz2 + (size_t)b * 3 * Mp;
    for (int m = t; m < Mp; m += 512) {
        float a = x2[m], e = x2[Mp + m], d = x2[2*Mp + m];
        float4 v; v.x = a; v.y = e; v.z = d; v.w = a*a + e*e + d*d;
        sp[m] = v;
    }
    __syncthreads();

    int n = blockIdx.x * 128 + qi;
    const float* x1 = xyz1 + (size_t)b * 3 * Nq;
    float qx = x1[n], qy = x1[Nq + n], qz = x1[2*Nq + n];
    float qq = qx*qx + qy*qy + qz*qz;

    float d2_0 = 1e30f, d2_1 = 1e30f, d2_2 = 1e30f;
    int   i0 = 0, i1 = 0, i2 = 0;
    int mbase = c * KCHLEN;
#pragma unroll 4
    for (int mm = 0; mm < KCHLEN; mm++) {
        int m = mbase + mm;
        float4 P = sp[m];
        float dot = qx*P.x + qy*P.y + qz*P.z;
        float d2  = qq + P.w - 2.0f*dot;       // matches reference's expanded form
        if (d2 < d2_2) {
            if (d2 < d2_1) {
                d2_2 = d2_1; i2 = i1;
                if (d2 < d2_0) { d2_1 = d2_0; i1 = i0; d2_0 = d2; i0 = m; }
                else           { d2_1 = d2;  i1 = m; }
            } else { d2_2 = d2; i2 = m; }
        }
    }
    cd[c*3+0][qi] = d2_0; ci[c*3+0][qi] = i0;
    cd[c*3+1][qi] = d2_1; ci[c*3+1][qi] = i1;
    cd[c*3+2][qi] = d2_2; ci[c*3+2][qi] = i2;
    __syncthreads();

    if (c == 0) {
        float b0 = 1e30f, b1 = 1e30f, b2 = 1e30f;
        int   j0 = 0, j1 = 0, j2 = 0;
#pragma unroll
        for (int r = 0; r < 12; r++) {
            float d2 = cd[r][qi];
            int   ix = ci[r][qi];
            if (d2 < b2) {
                if (d2 < b1) {
                    b2 = b1; j2 = j1;
                    if (d2 < b0) { b1 = b0; j1 = j0; b0 = d2; j0 = ix; }
                    else         { b1 = d2; j1 = ix; }
                } else { b2 = d2; j2 = ix; }
            }
        }
        float dist0 = sqrtf(fmaxf(b0, 1e-20f));
        float dist1 = sqrtf(fmaxf(b1, 1e-20f));
        float dist2 = sqrtf(fmaxf(b2, 1e-20f));

        const float* n1 = norm1 + (size_t)b * 3 * Nq;
        const float* n2 = norm2 + (size_t)b * 3 * Mp;
        float ax = n1[n], ay = n1[Nq+n], az = n1[2*Nq+n];
        float dx, dy, dz;
        dx = ax - n2[j0]; dy = ay - n2[Mp+j0]; dz = az - n2[2*Mp+j0];
        float nd0 = sqrtf(dx*dx + dy*dy + dz*dz);
        dx = ax - n2[j1]; dy = ay - n2[Mp+j1]; dz = az - n2[2*Mp+j1];
        float nd1 = sqrtf(dx*dx + dy*dy + dz*dz);
        dx = ax - n2[j2]; dy = ay - n2[Mp+j2]; dz = az - n2[2*Mp+j2];
        float nd2 = sqrtf(dx*dx + dy*dy + dz*dz);

        float r0 = 1.0f / fmaxf(dist0, 1e-10f);
        float r1 = 1.0f / fmaxf(dist1, 1e-10f);
        float r2 = 1.0f / fmaxf(dist2, 1e-10f);
        float rs = r0 + r1 + r2;
        float s0 = 1.0f / fmaxf(nd0, 1e-10f);
        float s1 = 1.0f / fmaxf(nd1, 1e-10f);
        float s2 = 1.0f / fmaxf(nd2, 1e-10f);
        float ssum = s0 + s1 + s2;
        sw[0][qi] = (r0 / rs) * (s0 / ssum);
        sw[1][qi] = (r1 / rs) * (s1 / ssum);
        sw[2][qi] = (r2 / rs) * (s2 / ssum);
        si[0][qi] = j0; si[1][qi] = j1; si[2][qi] = j2;
    }
    __syncthreads();

    // gather: thread handles channels [c*64, c*64+64) for query qi
    float w0 = sw[0][qi], w1 = sw[1][qi], w2 = sw[2][qi];
    int   j0 = si[0][qi], j1 = si[1][qi], j2 = si[2][qi];
    size_t col = (size_t)b * Nq + n;
    int ch0 = c * 64;
    const float4* p0 = (const float4*)(g_p2T + ((size_t)b*Mp + j0) * C2 + ch0);
    const float4* p1 = (const float4*)(g_p2T + ((size_t)b*Mp + j1) * C2 + ch0);
    const float4* p2 = (const float4*)(g_p2T + ((size_t)b*Mp + j2) * C2 + ch0);
    uint2* xh = (uint2*)(g_Xhi + col * CIN + ch0);
    uint2* xl = (uint2*)(g_Xlo + col * CIN + ch0);
#pragma unroll 4
    for (int cc = 0; cc < 16; cc++) {
        float4 a = p0[cc], bq = p1[cc], cq = p2[cc];
        float r[4];
        r[0] = w0*a.x + w1*bq.x + w2*cq.x;
        r[1] = w0*a.y + w1*bq.y + w2*cq.y;
        r[2] = w0*a.z + w1*bq.z + w2*cq.z;
        r[3] = w0*a.w + w1*bq.w + w2*cq.w;
        unsigned short h[4], l[4];
#pragma unroll
        for (int j = 0; j < 4; j++) split_bf(r[j], h[j], l[j]);
        xh[cc] = make_uint2((uint32_t)h[0] | ((uint32_t)h[1]<<16),
                            (uint32_t)h[2] | ((uint32_t)h[3]<<16));
        xl[cc] = make_uint2((uint32_t)l[0] | ((uint32_t)l[1]<<16),
                            (uint32_t)l[2] | ((uint32_t)l[3]<<16));
    }
}

// ---------------- GEMM0 (mma.sync bf16x3): D[ch 128][pt 128] --------------------
#define SMA_H 0
#define SMA_L 16384
#define SMB_H 32768
#define SMB_L 49152
#define G0_SMEM (128*132*4)     // 67584

__global__ __launch_bounds__(256, 1) void gemm0_mma_kernel(const float* __restrict__ bias)
{
    extern __shared__ char sm[];
    uint32_t smb = smem_u32(sm);
    int t = threadIdx.x, lid = t & 31, wid = t >> 5;
    int wm = wid >> 2, wn = wid & 3;          // warps 2(m) x 4(n)
    int c0 = blockIdx.x * 128;                // point tile
    int m0 = blockIdx.y * 128;                // channel tile
    int sub = lid >> 3, rr = lid & 7;

    float acc[4][4][4];
#pragma unroll
    for (int i = 0; i < 4; i++)
#pragma unroll
        for (int j = 0; j < 4; j++)
#pragma unroll
            for (int q = 0; q < 4; q++) acc[i][j][q] = 0.f;

    for (int ck = 0; ck < 6; ck++) {
        int kk = ck * 64;
        __syncthreads();
        for (int i = t; i < 128*8; i += 256) {
            int r = i >> 3, j = i & 7;
            uint32_t so = (uint32_t)(r*128 + ((j ^ (r & 7)) << 4));
            *(uint4*)(sm + SMA_H + so) = *(const uint4*)(g_W0h + (size_t)(m0 + r)*CIN + kk + j*8);
            *(uint4*)(sm + SMA_L + so) = *(const uint4*)(g_W0l + (size_t)(m0 + r)*CIN + kk + j*8);
            *(uint4*)(sm + SMB_H + so) = *(const uint4*)(g_Xhi + (size_t)(c0 + r)*CIN + kk + j*8);
            *(uint4*)(sm + SMB_L + so) = *(const uint4*)(g_Xlo + (size_t)(c0 + r)*CIN + kk + j*8);
        }
        __syncthreads();
#pragma unroll
        for (int kb = 0; kb < 4; kb++) {
            int chnk = kb*2 + (sub >> 1);
            uint32_t Ah[4][4], Al[4][4], Bh[4][2], Bl[4][2];
#pragma unroll
            for (int i = 0; i < 4; i++) {
                int row = wm*64 + i*16 + ((sub & 1) << 3) + rr;
                uint32_t so = (uint32_t)(row*128 + ((chnk ^ rr) << 4));
                LDSM4(Ah[i], smb + SMA_H + so);
                LDSM4(Al[i], smb + SMA_L + so);
            }
#pragma unroll
            for (int jj = 0; jj < 2; jj++) {
                int row = wn*32 + jj*16 + ((sub & 1) << 3) + rr;
                uint32_t so = (uint32_t)(row*128 + ((chnk ^ rr) << 4));
                uint32_t rg[4];
                LDSM4(rg, smb + SMB_H + so);
                Bh[jj*2][0] = rg[0]; Bh[jj*2+1][0] = rg[1];
                Bh[jj*2][1] = rg[2]; Bh[jj*2+1][1] = rg[3];
                LDSM4(rg, smb + SMB_L + so);
                Bl[jj*2][0] = rg[0]; Bl[jj*2+1][0] = rg[1];
                Bl[jj*2][1] = rg[2]; Bl[jj*2+1][1] = rg[3];
            }
#pragma unroll
            for (int i = 0; i < 4; i++)
#pragma unroll
                for (int jt = 0; jt < 4; jt++) {
                    mma_bf16(acc[i][jt], Ah[i], Bh[jt]);
                    mma_bf16(acc[i][jt], Ah[i], Bl[jt]);
                    mma_bf16(acc[i][jt], Al[i], Bh[jt]);
                }
        }
    }

    // epilogue: transpose through smem -> g_Y0T [pt][ch], bn0 partials
    __syncthreads();
    float* s32 = (float*)sm;
#pragma unroll
    for (int i = 0; i < 4; i++) {
        int chr = wm*64 + i*16 + (lid >> 2);
#pragma unroll
        for (int jt = 0; jt < 4; jt++) {
            int pt = wn*32 + jt*8 + (lid & 3)*2;
            s32[(size_t)pt*132 + chr]       = acc[i][jt][0];
            s32[(size_t)(pt+1)*132 + chr]   = acc[i][jt][1];
            s32[(size_t)pt*132 + chr + 8]   = acc[i][jt][2];
            s32[(size_t)(pt+1)*132 + chr+8] = acc[i][jt][3];
        }
    }
    __syncthreads();
    int chn = t & 127, half = t >> 7;
    float bi = bias[m0 + chn];
    float s = 0.f, q = 0.f;
    for (int p = half*64; p < half*64 + 64; p++) {
        float v = s32[(size_t)p*132 + chn] + bi;
        s += v; q += v*v;
        g_Y0T[(size_t)(c0 + p)*CO0 + m0 + chn] = v;
    }
    g_p0s[(size_t)(blockIdx.x*2 + half)*CO0 + m0 + chn] = s;
    g_p0q[(size_t)(blockIdx.x*2 + half)*CO0 + m0 + chn] = q;
}

// ---------------- bn0 partial reduce -> scale0/shift0 ---------------------------
__global__ __launch_bounds__(256) void reduce0_kernel(const float* __restrict__ g,
                                                      const float* __restrict__ be)
{
    int chn = blockIdx.x, t = threadIdx.x;
    double s = (double)g_p0s[(size_t)t*CO0 + chn] + (double)g_p0s[(size_t)(t+256)*CO0 + chn];
    double q = (double)g_p0q[(size_t)t*CO0 + chn] + (double)g_p0q[(size_t)(t+256)*CO0 + chn];
    __shared__ double ss[256], qq[256];
    ss[t] = s; qq[t] = q;
    __syncthreads();
    for (int st = 128; st > 0; st >>= 1) {
        if (t < st) { ss[t] += ss[t+st]; qq[t] += qq[t+st]; }
        __syncthreads();
    }
    if (t == 0) {
        double inv = 1.0 / (double)NC;
        double mean = ss[0] * inv;
        double var  = qq[0] * inv - mean*mean;
        double sc   = (double)g[chn] / sqrt(var + 1e-5);
        g_scale0[chn] = (float)sc;
        g_shift0[chn] = (float)((double)be[chn] - mean * sc);
    }
}

// ---------------- GEMM1 (mma.sync bf16x3): D[ch 128][pt 128] -> d_out -----------
#define G1_SMEM (65536 + 2048)

__global__ __launch_bounds__(256, 1) void gemm1_mma_kernel(const float* __restrict__ bias,
                                                           float* __restrict__ out)
{
    extern __shared__ char sm[];
    uint32_t smb = smem_u32(sm);
    float* s_sc = (float*)(sm + 65536);
    float* s_sh = (float*)(sm + 65536 + 1024);
    int t = threadIdx.x, lid = t & 31, wid = t >> 5;
    int wm = wid >> 2, wn = wid & 3;
    int p0 = blockIdx.x * 128;
    int sub = lid >> 3, rr = lid & 7;

    s_sc[t] = g_scale0[t];
    s_sh[t] = g_shift0[t];

    float acc[4][4][4];
#pragma unroll
    for (int i = 0; i < 4; i++)
#pragma unroll
        for (int j = 0; j < 4; j++)
#pragma unroll
            for (int q = 0; q < 4; q++) acc[i][j][q] = 0.f;

    for (int ck = 0; ck < 4; ck++) {
        int kk = ck * 64;
        __syncthreads();
        for (int i = t; i < 128*8; i += 256) {
            int r = i >> 3, j = i & 7;
            uint32_t so = (uint32_t)(r*128 + ((j ^ (r & 7)) << 4));
            *(uint4*)(sm + SMA_H + so) = *(const uint4*)(g_W1h + (size_t)r*CO0 + kk + j*8);
            *(uint4*)(sm + SMA_L + so) = *(const uint4*)(g_W1l + (size_t)r*CO0 + kk + j*8);
            const float* yp = g_Y0T + (size_t)(p0 + r)*CO0 + kk + j*8;
            float v[8];
#pragma unroll
            for (int q = 0; q < 8; q++) {
                int k = kk + j*8 + q;
                v[q] = fmaxf(0.f, fmaf(yp[q], s_sc[k], s_sh[k]));
            }
            uint4 h4, l4;
            split8(v, h4, l4);
            *(uint4*)(sm + SMB_H + so) = h4;
            *(uint4*)(sm + SMB_L + so) = l4;
        }
        __syncthreads();
#pragma unroll
        for (int kb = 0; kb < 4; kb++) {
            int chnk = kb*2 + (sub >> 1);
            uint32_t Ah[4][4], Al[4][4], Bh[4][2], Bl[4][2];
#pragma unroll
            for (int i = 0; i < 4; i++) {
                int row = wm*64 + i*16 + ((sub & 1) << 3) + rr;
                uint32_t so = (uint32_t)(row*128 + ((chnk ^ rr) << 4));
                LDSM4(Ah[i], smb + SMA_H + so);
                LDSM4(Al[i], smb + SMA_L + so);
            }
#pragma unroll
            for (int jj = 0; jj < 2; jj++) {
                int row = wn*32 + jj*16 + ((sub & 1) << 3) + rr;
                uint32_t so = (uint32_t)(row*128 + ((chnk ^ rr) << 4));
                uint32_t rg[4];
                LDSM4(rg, smb + SMB_H + so);
                Bh[jj*2][0] = rg[0]; Bh[jj*2+1][0] = rg[1];
                Bh[jj*2][1] = rg[2]; Bh[jj*2+1][1] = rg[3];
                LDSM4(rg, smb + SMB_L + so);
                Bl[jj*2][0] = rg[0]; Bl[jj*2+1][0] = rg[1];
                Bl[jj*2][1] = rg[2]; Bl[jj*2+1][1] = rg[3];
            }
#pragma unroll
            for (int i = 0; i < 4; i++)
#pragma unroll
                for (int jt = 0; jt < 4; jt++) {
                    mma_bf16(acc[i][jt], Ah[i], Bh[jt]);
                    mma_bf16(acc[i][jt], Ah[i], Bl[jt]);
                    mma_bf16(acc[i][jt], Al[i], Bh[jt]);
                }
        }
    }

#pragma unroll
    for (int i = 0; i < 4; i++) {
        int ch = wm*64 + i*16 + (lid >> 2);
        float b0v = bias[ch], b8v = bias[ch + 8];
#pragma unroll
        for (int jt = 0; jt < 4; jt++) {
            int ptl = wn*32 + jt*8 + (lid & 3)*2;
            int gp = p0 + ptl;
            int b = gp >> 13, n = gp & (Nq - 1);
            float2 v0 = make_float2(acc[i][jt][0] + b0v, acc[i][jt][1] + b0v);
            float2 v1 = make_float2(acc[i][jt][2] + b8v, acc[i][jt][3] + b8v);
            *(float2*)(out + ((size_t)b*CO1 + ch)*Nq + n)     = v0;
            *(float2*)(out + ((size_t)b*CO1 + ch + 8)*Nq + n) = v1;
        }
    }
}

// ---------------- per-channel BN stats (bn1 over d_out) -------------------------
__global__ __launch_bounds__(256) void stats_kernel(const float* __restrict__ Y,
    const float* __restrict__ g, const float* __restrict__ be,
    float* __restrict__ scale, float* __restrict__ shift,
    long long chan_stride, int nchunks, long long chunk_stride, int chunk_len, float inv_count)
{
    int o = blockIdx.x;
    int tid = threadIdx.x;
    float s = 0.f, q = 0.f;
    for (int cb = 0; cb < nchunks; cb++) {
        const float4* p = (const float4*)(Y + (size_t)o * chan_stride + (size_t)cb * chunk_stride);
        int len4 = chunk_len >> 2;
        for (int i = tid; i < len4; i += 256) {
            float4 v = p[i];
            s += (v.x + v.y) + (v.z + v.w);
            q += (v.x*v.x + v.y*v.y) + (v.z*v.z + v.w*v.w);
        }
    }
    __shared__ double ss[256], sq[256];
    ss[tid] = (double)s; sq[tid] = (double)q;
    __syncthreads();
    for (int st = 128; st > 0; st >>= 1) {
        if (tid < st) { ss[tid] += ss[tid+st]; sq[tid] += sq[tid+st]; }
        __syncthreads();
    }
    if (tid == 0) {
        double mean = ss[0] * (double)inv_count;
        double var  = sq[0] * (double)inv_count - mean*mean;
        double sc   = (double)g[o] / sqrt(var + 1e-5);
        scale[o] = (float)sc;
        shift[o] = (float)((double)be[o] - mean * sc);
    }
}

// ---------------- final BN + ReLU, in place on d_out ----------------------------
__global__ __launch_bounds__(256) void bnrelu_kernel(float* __restrict__ out)
{
    int i = blockIdx.x * 256 + threadIdx.x;
    int o = (i >> 11) & 127;
    float sc = g_scale1[o], sh = g_shift1[o];
    float4* p = (float4*)out;
    float4 v = p[i];
    v.x = fmaxf(0.f, fmaf(v.x, sc, sh));
    v.y = fmaxf(0.f, fmaf(v.y, sc, sh));
    v.z = fmaxf(0.f, fmaf(v.z, sc, sh));
    v.w = fmaxf(0.f, fmaf(v.w, sc, sh));
    p[i] = v;
}

// ---------------- launch ---------------------------------------------------------
extern "C" void kernel_launch(void* const* d_in, const int* in_sizes, int n_in,
                              void* d_out, int out_size)
{
    const float* xyz1    = (const float*)d_in[0];
    const float* xyz2    = (const float*)d_in[1];
    const float* norm1   = (const float*)d_in[2];
    const float* norm2   = (const float*)d_in[3];
    const float* points1 = (const float*)d_in[4];
    const float* points2 = (const float*)d_in[5];
    const float* W0      = (const float*)d_in[6];
    const float* b0      = (const float*)d_in[7];
    const float* g0      = (const float*)d_in[8];
    const float* be0     = (const float*)d_in[9];
    const float* W1      = (const float*)d_in[10];
    const float* b1      = (const float*)d_in[11];
    const float* g1      = (const float*)d_in[12];
    const float* be1     = (const float*)d_in[13];
    float* out = (float*)d_out;

    cudaFuncSetAttribute(gemm0_mma_kernel, cudaFuncAttributeMaxDynamicSharedMemorySize, G0_SMEM);
    cudaFuncSetAttribute(gemm1_mma_kernel, cudaFuncAttributeMaxDynamicSharedMemorySize, G1_SMEM);

    float *p2T_ptr, *sc1, *sh1;
    cudaGetSymbolAddress((void**)&p2T_ptr, g_p2T);
    cudaGetSymbolAddress((void**)&sc1, g_scale1);
    cudaGetSymbolAddress((void**)&sh1, g_shift1);

    // weight presplit (bf16 hi/lo)
    splitw_kernel<<<(CO0*CIN + CO1*CO0 + 255)/256, 256>>>(W0, W1);
    // points2 (B,256,2048) -> g_p2T (B,2048,256) fp32
    transpose_kernel<<<dim3(Mp/32, C2/32, Bsz), dim3(32,8)>>>(points2, p2T_ptr, C2, Mp, C2);
    // points1 -> split bf16 into g_Xhi/lo [col][256..383]
    transpose_split_kernel<<<dim3(Nq/32, C1/32, Bsz), dim3(32,8)>>>(points1);
    // 3-NN + interpolation -> g_Xhi/lo [col][0..255]
    knn_interp_kernel<<<dim3(Nq/128, Bsz), 512>>>(xyz1, xyz2, norm1, norm2);
    // conv0 (HMMA bf16x3) -> g_Y0T [pt][ch] + bn0 partials
    gemm0_mma_kernel<<<dim3(NC/128, CO0/128), 256, G0_SMEM>>>(b0);
    // bn0 affine
    reduce0_kernel<<<CO0, 256>>>(g0, be0);
    // conv1 (HMMA bf16x3, bn0+relu fused in staging) -> d_out raw
    gemm1_mma_kernel<<<dim3(NC/128), 256, G1_SMEM>>>(b1, out);
    // bn1 stats over d_out raw
    stats_kernel<<<CO1, 256>>>(out, g1, be1, sc1, sh1,
                               (long long)Nq, Bsz, (long long)(CO1*Nq), Nq, 1.0f/(float)NC);
    // final bn1 + relu in place
    bnrelu_kernel<<<(Bsz*CO1*Nq/4)/256, 256>>>(out);
}